// round 14
// baseline (speedup 1.0000x reference)
#include <cuda_runtime.h>
#include <cuda_fp16.h>
#include <stdint.h>
#include <stddef.h>

#define BB 2048
#define TT 100
#define EE 512
#define POSE 34
#define FUT 10
#define BE (BB*EE)

#define K1 576        // cell1: 512 (h1) + 64 (x slab: 34 real + pad)
#define K2 1024       // cell2: 512 (h1_new) + 512 (h2)
#define KD 512        // decoder

#define NCTA 256      // persistent grid; 2/SM on 128 SMs, all co-resident
#define NPHASE (TT+1+FUT)

// SMEM pipeline: 5 stages x 16KB (A 8K | B 8K); single sync per chunk (WAR-safe at 5 stages)
#define STAGE_BYTES 16384
#define OFF_A 0
#define OFF_B 8192
#define NSTAGE 5
#define SMEM_TOTAL (NSTAGE*STAGE_BYTES)

// ---------------- device globals (no allocation allowed) ----------------
__device__ __align__(16) __half g_h1[2][BE];     // h1(t) lives in slot t&1
__device__ __align__(16) __half g_h2[2][BE];     // h2(t) lives in slot t&1
__device__ __align__(16) __half g_dh[2][BE];     // decoder h, slot f&1
__device__ __align__(16) float g_c1[BE], g_c2[BE];
__device__ __align__(16) __half g_W1[2048*K1];
__device__ __align__(16) __half g_W2[2048*K2];
__device__ __align__(16) __half g_WD1[2048*KD];
__device__ __align__(16) __half g_WDr[2048*KD];
__device__ __align__(16) __half g_x[(size_t)TT*BB*64];
__device__ __align__(16) float g_b1[2048], g_b2[2048], g_bd[2048];
__device__ __align__(16) float g_preds[(size_t)FUT*BE];

// global barrier state (returns to cnt=0 after every barrier -> graph-replay safe)
__device__ unsigned g_cnt = 0;
__device__ volatile unsigned g_gen = 0;

// ---------------- helpers ----------------
__device__ __forceinline__ float sigmoidf_(float x) { return __fdividef(1.f, 1.f + __expf(-x)); }
__device__ __forceinline__ float tanhf_(float x)    { return 1.f - __fdividef(2.f, __expf(2.f*x) + 1.f); }

__device__ __forceinline__ uint32_t smem_u32(const void* p) {
    uint32_t a;
    asm("{ .reg .u64 t; cvta.to.shared.u64 t, %1; cvt.u32.u64 %0, t; }" : "=r"(a) : "l"(p));
    return a;
}

// Interleaved tile layout: tile is 128 rows x 32 k (f16). Physical: 64 rows x 128B.
// element (row, kk): physrow r = row>>1, chunk = ((row&1)*4 + (kk>>3)) ^ (r&7),
// byte = r*128 + chunk*16 + (kk&7)*2.  Conflict-free for cp.async STS and ldmatrix.
__device__ __forceinline__ uint32_t tile_addr(uint32_t base, int row, int kk) {
    int r = row >> 1;
    int c = (((row & 1) << 2) + (kk >> 3)) ^ (r & 7);
    return base + (uint32_t)(r * 128 + c * 16 + (kk & 7) * 2);
}

__device__ __forceinline__ void cp16(uint32_t s, const void* g) {
    asm volatile("cp.async.cg.shared.global [%0], [%1], 16;" :: "r"(s), "l"(g));
}
__device__ __forceinline__ void cp_commit() { asm volatile("cp.async.commit_group;"); }
__device__ __forceinline__ void cp_wait3()  { asm volatile("cp.async.wait_group 3;"); }
__device__ __forceinline__ void cp_wait0()  { asm volatile("cp.async.wait_group 0;"); }

__device__ __forceinline__ void ldsm4(uint32_t* d, uint32_t a) {
    asm volatile("ldmatrix.sync.aligned.m8n8.x4.shared.b16 {%0,%1,%2,%3}, [%4];"
        : "=r"(d[0]), "=r"(d[1]), "=r"(d[2]), "=r"(d[3]) : "r"(a));
}
__device__ __forceinline__ void mma_f16(float* d, const uint32_t* a, const uint32_t* b) {
    asm volatile("mma.sync.aligned.m16n8k16.row.col.f32.f16.f16.f32 "
        "{%0,%1,%2,%3}, {%4,%5,%6,%7}, {%8,%9}, {%0,%1,%2,%3};"
        : "+f"(d[0]), "+f"(d[1]), "+f"(d[2]), "+f"(d[3])
        : "r"(a[0]), "r"(a[1]), "r"(a[2]), "r"(a[3]), "r"(b[0]), "r"(b[1]));
}

// device-wide sense-reversing barrier (all NCTA CTAs co-resident)
__device__ __forceinline__ void grid_bar() {
    __syncthreads();
    if (threadIdx.x == 0) {
        __threadfence();
        unsigned my = g_gen;
        if (atomicAdd(&g_cnt, 1u) == NCTA - 1u) {
            atomicExch(&g_cnt, 0u);
            __threadfence();
            g_gen = my + 1u;
        } else {
            while (g_gen == my) {}
        }
        __threadfence();
    }
    __syncthreads();
}

// ============ fused mma.sync LSTM tile body (fp16, 256 threads, warp tile 64x32) ============
// gates[m][n] = sum_k A[m][k]*W[n][k] + bias[n]
// A = concat(A0[0:K0], A1[K0:Ktot]); n gate-interleaved: cols 4e..4e+3 = (i,f,g,o) of unit e.
__device__ __forceinline__ void lstm_tile_body(
    const __half* __restrict__ A0, int lda0,
    const __half* __restrict__ A1, int lda1,
    int K0, int Ktot,
    const __half* __restrict__ W, int ldw,
    const float* __restrict__ bias,
    float* __restrict__ c_inout,
    __half* __restrict__ H,
    float* __restrict__ Hf,
    int n0, int m0)
{
    extern __shared__ char smem[];
    const uint32_t sbase = smem_u32(smem);
    const int tid  = threadIdx.x;
    const int lane = tid & 31;
    const int warp = tid >> 5;         // 0..7
    const int wm = warp >> 2;          // 0..1  (m 64-half)
    const int wn = warp & 3;           // 0..3  (n 32-quarter)

    const int NC = Ktot >> 5;          // 32-k chunks

    // ---- stage issue: 4 cp.async per thread (A x2, B x2) over 256 threads ----
    auto issue = [&](int st) {
        const int kstW = st << 5;
        int kstA = kstW;
        const char* pA = (const char*)A0;
        int lda = lda0;
        if (kstA >= K0) { pA = (const char*)A1; lda = lda1; kstA -= K0; }
        const uint32_t sb = sbase + (uint32_t)((st % NSTAGE) * STAGE_BYTES);
#pragma unroll
        for (int p = 0; p < 2; p++) {
            const int ch = tid + p * 256;
            const int row = ch >> 2, c = ch & 3;
            cp16(tile_addr(sb + OFF_A, row, c * 8),
                 pA + ((size_t)(m0 + row) * lda + kstA + c * 8) * 2);
            cp16(tile_addr(sb + OFF_B, row, c * 8),
                 (const char*)W + ((size_t)(n0 + row) * ldw + kstW + c * 8) * 2);
        }
        cp_commit();
    };

    issue(0); issue(1); issue(2);

    float acc[16][4];                   // [i*4+j]  i: m16 idx 0..3, j: n8 idx 0..3
#pragma unroll
    for (int i = 0; i < 16; i++)
#pragma unroll
        for (int j = 0; j < 4; j++) acc[i][j] = 0.f;

    // lane-derived ldmatrix row/col offsets
    const int laA_r = lane & 15;            // row within m16
    const int laA_k = (lane >> 4) * 8;      // k half
    const int laB_r = (lane & 7) + ((lane >> 4) & 1) * 8;   // n within 16
    const int laB_k = ((lane >> 3) & 1) * 8;                // k half

#pragma unroll 1
    for (int cs = 0; cs < NC; cs++) {
        if (cs + 3 < NC) issue(cs + 3); else cp_commit();
        cp_wait3();
        __syncthreads();

        const uint32_t sb = sbase + (uint32_t)((cs % NSTAGE) * STAGE_BYTES);

#pragma unroll
        for (int h = 0; h < 2; h++) {
            const int kk0 = h * 16;
            uint32_t Af[4][4], Bf[8];
#pragma unroll
            for (int i = 0; i < 4; i++)
                ldsm4(Af[i], tile_addr(sb + OFF_A, wm * 64 + i * 16 + laA_r, kk0 + laA_k));
            ldsm4(&Bf[0], tile_addr(sb + OFF_B, wn * 32 + laB_r,      kk0 + laB_k));
            ldsm4(&Bf[4], tile_addr(sb + OFF_B, wn * 32 + 16 + laB_r, kk0 + laB_k));
#pragma unroll
            for (int i = 0; i < 4; i++)
#pragma unroll
                for (int j = 0; j < 4; j++)
                    mma_f16(acc[i * 4 + j], Af[i], &Bf[j * 2]);
        }
    }
    cp_wait0();   // drain outstanding prefetches before smem is reused for next job

    // ---- fused LSTM epilogue (register-resident) ----
    const int pairpos = lane & 1;
    const int rbase = lane >> 2;
    const int elocal = (lane >> 1) & 1;

#pragma unroll
    for (int i = 0; i < 4; i++) {
#pragma unroll
        for (int j = 0; j < 4; j++) {
            float* a = acc[i * 4 + j];
            float r0 = __shfl_xor_sync(0xffffffffu, a[0], 1);
            float r1 = __shfl_xor_sync(0xffffffffu, a[1], 1);
            float r2 = __shfl_xor_sync(0xffffffffu, a[2], 1);
            float r3 = __shfl_xor_sync(0xffffffffu, a[3], 1);
            float gi, gf, gg, go;
            if (pairpos == 0) { gi = a[0]; gf = a[1]; gg = r0; go = r1; }   // row rbase
            else              { gi = r2;  gf = r3;  gg = a[2]; go = a[3]; } // row rbase+8
            const int m = m0 + wm * 64 + i * 16 + rbase + pairpos * 8;
            const int e = ((n0 + wn * 32 + j * 8) >> 2) + elocal;

            const float4 bq = ((const float4*)bias)[e];
            gi += bq.x; gf += bq.y; gg += bq.z; go += bq.w;

            const size_t off = (size_t)m * EE + e;
            const float co = c_inout[off];
            const float cn = sigmoidf_(gf) * co + sigmoidf_(gi) * tanhf_(gg);
            const float hn = sigmoidf_(go) * tanhf_(cn);
            c_inout[off] = cn;
            H[off] = __float2half_rn(hn);
            if (Hf) Hf[off] = hn;
        }
    }
}

// ============ persistent kernel: whole recurrence (R10 structure, 256-thread core) ============
__global__ void __launch_bounds__(256, 2)
lstm_persistent()
{
    const int n0 = (blockIdx.x & 15) * 128;
    const int m0 = (blockIdx.x >> 4) * 128;

    const __half* h1b = (const __half*)g_h1;
    const __half* h2b = (const __half*)g_h2;

    // encoder: phase ph runs cell2(ph-1) then cell1(ph)
#pragma unroll 1
    for (int ph = 0; ph <= TT; ph++) {
#pragma unroll 1
        for (int j = 0; j < 2; j++) {
            const bool act = (j == 0) ? (ph >= 1) : (ph < TT);
            if (!act) continue;
            const int t = (j == 0) ? ph - 1 : ph;
            const __half* a0 = h1b + (size_t)(((j == 0) ? t : (t + 1)) & 1) * BE;
            const __half* a1 = (j == 0) ? (h2b + (size_t)((t + 1) & 1) * BE)
                                        : (g_x + (size_t)t * BB * 64);
            const int lda1   = (j == 0) ? EE : 64;
            const int kt     = (j == 0) ? K2 : K1;
            const __half* w  = (j == 0) ? g_W2 : g_W1;
            const float* bs  = (j == 0) ? g_b2 : g_b1;
            float* cc        = (j == 0) ? g_c2 : g_c1;
            __half* hh       = (j == 0) ? (g_h2[t & 1]) : (g_h1[t & 1]);
            lstm_tile_body(a0, EE, a1, lda1, 512, kt, w, kt, bs, cc, hh, nullptr, n0, m0);
        }
        grid_bar();
    }

    // decoder: f=0 uses Whh only with A=h2(99) (slot 1); f>=1 uses (Wih+Whh) with A=dh(f-1)
#pragma unroll 1
    for (int f = 0; f < FUT; f++) {
        const __half* a0 = (f == 0) ? (h2b + (size_t)BE)
                                    : ((const __half*)g_dh + (size_t)((f + 1) & 1) * BE);
        const __half* w  = (f == 0) ? g_WD1 : g_WDr;
        lstm_tile_body(a0, EE, nullptr, 0, KD, KD, w, KD, g_bd, g_c2,
                       g_dh[f & 1], g_preds + (size_t)f * BE, n0, m0);
        grid_bar();
    }
}

// ============ prep kernels ============
// permuted gate col n -> original row r = (n%4)*512 + n/4  (quad (i,f,g,o) per hidden e)
__global__ void prep_weights(const float* __restrict__ e1Whh,
                             const float* __restrict__ e2Wih, const float* __restrict__ e2Whh,
                             const float* __restrict__ d1Wih, const float* __restrict__ d1Whh,
                             const float* __restrict__ e2bih, const float* __restrict__ e2bhh,
                             const float* __restrict__ d1bih, const float* __restrict__ d1bhh)
{
    int n = blockIdx.y;
    int kk = blockIdx.x * 256 + threadIdx.x;
    if (kk >= K1 + K2 + KD + KD) return;
    int r = (n & 3) * 512 + (n >> 2);
    float v; __half* ph; long o;
    if (kk < K1) {
        v = (kk < 512) ? e1Whh[(long)r * 512 + kk] : 0.f;   // 512..575 pad; 512..545 overwritten by prep_wc
        ph = g_W1; o = (long)n * K1 + kk;
    } else if (kk < K1 + K2) {
        int k = kk - K1;
        v = (k < 512) ? e2Wih[(long)r * 512 + k] : e2Whh[(long)r * 512 + (k - 512)];
        ph = g_W2; o = (long)n * K2 + k;
    } else if (kk < K1 + K2 + KD) {
        int k = kk - (K1 + K2);
        v = d1Whh[(long)r * 512 + k];
        ph = g_WD1; o = (long)n * KD + k;
    } else {
        int k = kk - (K1 + K2 + KD);
        v = d1Wih[(long)r * 512 + k] + d1Whh[(long)r * 512 + k];
        ph = g_WDr; o = (long)n * KD + k;
    }
    ph[o] = __float2half_rn(v);
    if (kk == 0) {
        g_b2[n] = e2bih[r] + e2bhh[r];
        g_bd[n] = d1bih[r] + d1bhh[r];
    }
}

// Wc = e1Wih @ enc_lin_W folded into W1 rows 512..545; b1 = e1Wih·enc_b + biases
__global__ void prep_wc(const float* __restrict__ e1Wih,
                        const float* __restrict__ encW, const float* __restrict__ encb,
                        const float* __restrict__ e1bih, const float* __restrict__ e1bhh)
{
    int n = blockIdx.x;
    int r = (n & 3) * 512 + (n >> 2);
    __shared__ float wr[512];
    for (int e = threadIdx.x; e < 512; e += blockDim.x) wr[e] = e1Wih[(long)r * 512 + e];
    __syncthreads();
    int t = threadIdx.x;
    if (t < POSE) {
        float acc = 0.f;
        for (int e = 0; e < 512; e++) acc = fmaf(wr[e], encW[e * POSE + t], acc);
        g_W1[(long)n * K1 + 512 + t] = __float2half_rn(acc);
    } else if (t == POSE) {
        float acc = e1bih[r] + e1bhh[r];
        for (int e = 0; e < 512; e++) acc = fmaf(wr[e], encb[e], acc);
        g_b1[n] = acc;
    }
}

__global__ void prep_x(const float* __restrict__ x) {
    long idx = (long)blockIdx.x * 256 + threadIdx.x;
    if (idx >= (long)TT * BB * 64) return;
    int c = (int)(idx & 63);
    int b = (int)((idx >> 6) & (BB - 1));
    int t = (int)(idx >> 17);
    float v = (c < POSE) ? x[(long)b * (TT * POSE) + t * POSE + c] : 0.f;
    g_x[idx] = __float2half_rn(v);
}

__global__ void zero_init() {
    long i = (long)blockIdx.x * 256 + threadIdx.x;
    if (i < (long)BE) {
        __half z = __float2half_rn(0.f);
        g_h1[1][i] = z;     // h1(-1) read from slot 1
        g_h2[1][i] = z;     // h2(-1) read from slot 1
        g_c1[i] = 0.f; g_c2[i] = 0.f;
    }
}

__global__ void final_linear(const float* __restrict__ preds,
                             const float* __restrict__ W, const float* __restrict__ bias,
                             float* __restrict__ out)
{
    int bf = blockIdx.x;
    int f = bf % FUT;
    int b = bf / FUT;
    __shared__ float row[512];
    const float* src = preds + ((size_t)f * BB + b) * EE;
    for (int i = threadIdx.x; i < 512; i += blockDim.x) row[i] = src[i];
    __syncthreads();
    int p = threadIdx.x;
    if (p < POSE) {
        const float* w = W + (size_t)p * 512;
        float acc = bias[p];
        for (int e = 0; e < 512; e++) acc = fmaf(row[e], w[e], acc);
        out[(size_t)b * (FUT * POSE) + f * POSE + p] = acc;
    }
}

// ============ launch ============
extern "C" void kernel_launch(void* const* d_in, const int* in_sizes, int n_in,
                              void* d_out, int out_size)
{
    (void)in_sizes; (void)n_in; (void)out_size;
    const float* x     = (const float*)d_in[0];
    const float* encW  = (const float*)d_in[1];
    const float* encb  = (const float*)d_in[2];
    const float* e1Wih = (const float*)d_in[3];
    const float* e1Whh = (const float*)d_in[4];
    const float* e1bih = (const float*)d_in[5];
    const float* e1bhh = (const float*)d_in[6];
    const float* e2Wih = (const float*)d_in[7];
    const float* e2Whh = (const float*)d_in[8];
    const float* e2bih = (const float*)d_in[9];
    const float* e2bhh = (const float*)d_in[10];
    const float* d1Wih = (const float*)d_in[11];
    const float* d1Whh = (const float*)d_in[12];
    const float* d1bih = (const float*)d_in[13];
    const float* d1bhh = (const float*)d_in[14];
    const float* dW    = (const float*)d_in[15];
    const float* db    = (const float*)d_in[16];
    float* out = (float*)d_out;

    float* preds;
    cudaGetSymbolAddress((void**)&preds, g_preds);

    cudaFuncSetAttribute(lstm_persistent, cudaFuncAttributeMaxDynamicSharedMemorySize, SMEM_TOTAL);

    zero_init<<<(BE + 255) / 256, 256>>>();
    prep_weights<<<dim3((K1 + K2 + 2 * KD + 255) / 256, 2048), 256>>>(
        e1Whh, e2Wih, e2Whh, d1Wih, d1Whh, e2bih, e2bhh, d1bih, d1bhh);
    prep_wc<<<2048, 64>>>(e1Wih, encW, encb, e1bih, e1bhh);
    prep_x<<<(int)(((long)TT * BB * 64 + 255) / 256), 256>>>(x);

    // entire recurrence: one persistent launch, device-wide barriers between phases
    lstm_persistent<<<NCTA, 256, SMEM_TOTAL>>>();

    final_linear<<<BB * FUT, 64>>>(preds, dW, db, out);
}

// round 15
// speedup vs baseline: 1.0703x; 1.0703x over previous
#include <cuda_runtime.h>
#include <cuda_fp16.h>
#include <stdint.h>
#include <stddef.h>

#define BB 2048
#define TT 100
#define EE 512
#define POSE 34
#define FUT 10
#define BE (BB*EE)

#define K1 576        // cell1: 512 (h1) + 64 (x slab: 34 real + pad)
#define K2 1024       // cell2: 512 (h1_new) + 512 (h2)
#define KD 512        // decoder

#define NCTA 256      // persistent grid; 2/SM on 128 SMs, all co-resident
#define NPHASE (TT+1+FUT)

// SMEM pipeline: 5 stages x 16KB (A 8K | B 8K); single sync per chunk (WAR-safe at 5 stages)
#define STAGE_BYTES 16384
#define OFF_A 0
#define OFF_B 8192
#define NSTAGE 5
#define SMEM_TOTAL (NSTAGE*STAGE_BYTES)

// ---------------- device globals (no allocation allowed) ----------------
__device__ __align__(16) __half g_h1[2][BE];     // h1(t) lives in slot t&1
__device__ __align__(16) __half g_h2[2][BE];     // h2(t) lives in slot t&1
__device__ __align__(16) __half g_dh[2][BE];     // decoder h, slot f&1
__device__ __align__(16) float g_c1[BE], g_c2[BE];
__device__ __align__(16) __half g_W1[2048*K1];
__device__ __align__(16) __half g_W2[2048*K2];
__device__ __align__(16) __half g_WD1[2048*KD];
__device__ __align__(16) __half g_WDr[2048*KD];
__device__ __align__(16) __half g_x[(size_t)TT*BB*64];
__device__ __align__(16) float g_b1[2048], g_b2[2048], g_bd[2048];
__device__ __align__(16) float g_preds[(size_t)FUT*BE];

// global barrier state (returns to cnt=0 after every barrier -> graph-replay safe)
__device__ unsigned g_cnt = 0;
__device__ volatile unsigned g_gen = 0;

// ---------------- helpers ----------------
__device__ __forceinline__ float sigmoidf_(float x) { return __fdividef(1.f, 1.f + __expf(-x)); }
__device__ __forceinline__ float tanhf_(float x)    { return 1.f - __fdividef(2.f, __expf(2.f*x) + 1.f); }

__device__ __forceinline__ uint32_t smem_u32(const void* p) {
    uint32_t a;
    asm("{ .reg .u64 t; cvta.to.shared.u64 t, %1; cvt.u32.u64 %0, t; }" : "=r"(a) : "l"(p));
    return a;
}

// Interleaved tile layout: tile is 128 rows x 32 k (f16). Physical: 64 rows x 128B.
// element (row, kk): physrow r = row>>1, chunk = ((row&1)*4 + (kk>>3)) ^ (r&7),
// byte = r*128 + chunk*16 + (kk&7)*2.  Conflict-free for cp.async STS and ldmatrix.
__device__ __forceinline__ uint32_t tile_addr(uint32_t base, int row, int kk) {
    int r = row >> 1;
    int c = (((row & 1) << 2) + (kk >> 3)) ^ (r & 7);
    return base + (uint32_t)(r * 128 + c * 16 + (kk & 7) * 2);
}

__device__ __forceinline__ void cp16(uint32_t s, const void* g) {
    asm volatile("cp.async.cg.shared.global [%0], [%1], 16;" :: "r"(s), "l"(g));
}
__device__ __forceinline__ void cp_commit() { asm volatile("cp.async.commit_group;"); }
__device__ __forceinline__ void cp_wait3()  { asm volatile("cp.async.wait_group 3;"); }
__device__ __forceinline__ void cp_wait0()  { asm volatile("cp.async.wait_group 0;"); }

__device__ __forceinline__ void ldsm4(uint32_t* d, uint32_t a) {
    asm volatile("ldmatrix.sync.aligned.m8n8.x4.shared.b16 {%0,%1,%2,%3}, [%4];"
        : "=r"(d[0]), "=r"(d[1]), "=r"(d[2]), "=r"(d[3]) : "r"(a));
}
__device__ __forceinline__ void mma_f16(float* d, const uint32_t* a, const uint32_t* b) {
    asm volatile("mma.sync.aligned.m16n8k16.row.col.f32.f16.f16.f32 "
        "{%0,%1,%2,%3}, {%4,%5,%6,%7}, {%8,%9}, {%0,%1,%2,%3};"
        : "+f"(d[0]), "+f"(d[1]), "+f"(d[2]), "+f"(d[3])
        : "r"(a[0]), "r"(a[1]), "r"(a[2]), "r"(a[3]), "r"(b[0]), "r"(b[1]));
}

// device-wide sense-reversing barrier (all NCTA CTAs co-resident)
__device__ __forceinline__ void grid_bar() {
    __syncthreads();
    if (threadIdx.x == 0) {
        __threadfence();
        unsigned my = g_gen;
        if (atomicAdd(&g_cnt, 1u) == NCTA - 1u) {
            atomicExch(&g_cnt, 0u);
            __threadfence();
            g_gen = my + 1u;
        } else {
            while (g_gen == my) {}
        }
        __threadfence();
    }
    __syncthreads();
}

// ============ fused mma.sync LSTM tile body (fp16, warp tile 64x64, 4 warps) ============
// gates[m][n] = sum_k A[m][k]*W[n][k] + bias[n]
// A = concat(A0[0:K0], A1[K0:Ktot]); n gate-interleaved: cols 4e..4e+3 = (i,f,g,o) of unit e.
__device__ __forceinline__ void lstm_tile_body(
    const __half* __restrict__ A0, int lda0,
    const __half* __restrict__ A1, int lda1,
    int K0, int Ktot,
    const __half* __restrict__ W, int ldw,
    const float* __restrict__ bias,
    float* __restrict__ c_inout,
    __half* __restrict__ H,
    float* __restrict__ Hf,
    int n0, int m0)
{
    extern __shared__ char smem[];
    const uint32_t sbase = smem_u32(smem);
    const int tid  = threadIdx.x;
    const int lane = tid & 31;
    const int warp = tid >> 5;         // 0..3
    const int wm = warp >> 1;          // 0..1  (m 64-half)
    const int wn = warp & 1;           // 0..1  (n 64-half)

    const int NC = Ktot >> 5;          // 32-k chunks

    // ---- stage issue: 8 cp.async per thread (A x4, B x4) ----
    auto issue = [&](int st) {
        const int kstW = st << 5;
        int kstA = kstW;
        const char* pA = (const char*)A0;
        int lda = lda0;
        if (kstA >= K0) { pA = (const char*)A1; lda = lda1; kstA -= K0; }
        const uint32_t sb = sbase + (uint32_t)((st % NSTAGE) * STAGE_BYTES);
#pragma unroll
        for (int p = 0; p < 4; p++) {
            const int ch = tid + p * 128;
            const int row = ch >> 2, c = ch & 3;
            cp16(tile_addr(sb + OFF_A, row, c * 8),
                 pA + ((size_t)(m0 + row) * lda + kstA + c * 8) * 2);
            cp16(tile_addr(sb + OFF_B, row, c * 8),
                 (const char*)W + ((size_t)(n0 + row) * ldw + kstW + c * 8) * 2);
        }
        cp_commit();
    };

    issue(0);
    issue(1);
    issue(2);

    float acc[32][4];                   // [i*8+jj][..]  i: m16 idx 0..3, jj: n8 idx 0..7
#pragma unroll
    for (int i = 0; i < 32; i++)
#pragma unroll
        for (int j = 0; j < 4; j++) acc[i][j] = 0.f;

    // lane-derived ldmatrix row/col offsets
    const int laA_r = lane & 15;            // row within m16
    const int laA_k = (lane >> 4) * 8;      // k half
    const int laB_r = (lane & 7) + ((lane >> 4) & 1) * 8;   // n within 16
    const int laB_k = ((lane >> 3) & 1) * 8;                // k half

#pragma unroll 1
    for (int cs = 0; cs < NC; cs++) {
        if (cs + 3 < NC) issue(cs + 3); else cp_commit();
        cp_wait3();
        __syncthreads();

        const uint32_t sb = sbase + (uint32_t)((cs % NSTAGE) * STAGE_BYTES);

        // ---- preload ALL fragments for the whole 32-k chunk, then mma straight ----
        uint32_t Af[2][4][4], Bf[2][16];
#pragma unroll
        for (int h = 0; h < 2; h++) {
            const int kk0 = h * 16;
#pragma unroll
            for (int i = 0; i < 4; i++)
                ldsm4(Af[h][i], tile_addr(sb + OFF_A, wm * 64 + i * 16 + laA_r, kk0 + laA_k));
#pragma unroll
            for (int j = 0; j < 4; j++)
                ldsm4(&Bf[h][j * 4], tile_addr(sb + OFF_B, wn * 64 + j * 16 + laB_r, kk0 + laB_k));
        }
#pragma unroll
        for (int h = 0; h < 2; h++)
#pragma unroll
            for (int i = 0; i < 4; i++)
#pragma unroll
                for (int jj = 0; jj < 8; jj++)
                    mma_f16(acc[i * 8 + jj], Af[h][i], &Bf[h][jj * 2]);
    }
    cp_wait0();   // drain outstanding prefetches before smem is reused next call

    // ---- fused LSTM epilogue (register-resident) ----
    // per 16x8 mma tile: lane covers rows (lane>>2)+{0,8}, col pair (lane&3)*2+{0,1}.
    // pair (lane, lane^1) jointly owns a gate quad; shfl_xor(1) assembles it.
    const int pairpos = lane & 1;
    const int rbase = lane >> 2;
    const int elocal = (lane >> 1) & 1;

#pragma unroll
    for (int i = 0; i < 4; i++) {
#pragma unroll
        for (int jj = 0; jj < 8; jj++) {
            float* a = acc[i * 8 + jj];
            float r0 = __shfl_xor_sync(0xffffffffu, a[0], 1);
            float r1 = __shfl_xor_sync(0xffffffffu, a[1], 1);
            float r2 = __shfl_xor_sync(0xffffffffu, a[2], 1);
            float r3 = __shfl_xor_sync(0xffffffffu, a[3], 1);
            float gi, gf, gg, go;
            if (pairpos == 0) { gi = a[0]; gf = a[1]; gg = r0; go = r1; }
            else              { gi = r2;  gf = r3;  gg = a[2]; go = a[3]; }
            const int m = m0 + wm * 64 + i * 16 + rbase + pairpos * 8;
            const int e = ((n0 + wn * 64 + jj * 8) >> 2) + elocal;

            const float4 bq = ((const float4*)bias)[e];
            gi += bq.x; gf += bq.y; gg += bq.z; go += bq.w;

            const size_t off = (size_t)m * EE + e;
            const float co = c_inout[off];
            const float cn = sigmoidf_(gf) * co + sigmoidf_(gi) * tanhf_(gg);
            const float hn = sigmoidf_(go) * tanhf_(cn);
            c_inout[off] = cn;
            H[off] = __float2half_rn(hn);
            if (Hf) Hf[off] = hn;
        }
    }
}

// ============ persistent kernel: whole recurrence in one launch (R10 structure) ============
__global__ void __launch_bounds__(128, 2)
lstm_persistent()
{
    const int n0 = (blockIdx.x & 15) * 128;
    const int m0 = (blockIdx.x >> 4) * 128;

    const __half* h1b = (const __half*)g_h1;
    const __half* h2b = (const __half*)g_h2;

    // encoder: phase ph runs cell2(ph-1) then cell1(ph)
#pragma unroll 1
    for (int ph = 0; ph <= TT; ph++) {
#pragma unroll 1
        for (int j = 0; j < 2; j++) {
            const bool act = (j == 0) ? (ph >= 1) : (ph < TT);
            if (!act) continue;
            const int t = (j == 0) ? ph - 1 : ph;
            const __half* a0 = h1b + (size_t)(((j == 0) ? t : (t + 1)) & 1) * BE;
            const __half* a1 = (j == 0) ? (h2b + (size_t)((t + 1) & 1) * BE)
                                        : (g_x + (size_t)t * BB * 64);
            const int lda1   = (j == 0) ? EE : 64;
            const int kt     = (j == 0) ? K2 : K1;
            const __half* w  = (j == 0) ? g_W2 : g_W1;
            const float* bs  = (j == 0) ? g_b2 : g_b1;
            float* cc        = (j == 0) ? g_c2 : g_c1;
            __half* hh       = (j == 0) ? (g_h2[t & 1]) : (g_h1[t & 1]);
            lstm_tile_body(a0, EE, a1, lda1, 512, kt, w, kt, bs, cc, hh, nullptr, n0, m0);
        }
        grid_bar();
    }

    // decoder: f=0 uses Whh only with A=h2(99) (slot 1); f>=1 uses (Wih+Whh) with A=dh(f-1)
#pragma unroll 1
    for (int f = 0; f < FUT; f++) {
        const __half* a0 = (f == 0) ? (h2b + (size_t)BE)
                                    : ((const __half*)g_dh + (size_t)((f + 1) & 1) * BE);
        const __half* w  = (f == 0) ? g_WD1 : g_WDr;
        lstm_tile_body(a0, EE, nullptr, 0, KD, KD, w, KD, g_bd, g_c2,
                       g_dh[f & 1], g_preds + (size_t)f * BE, n0, m0);
        grid_bar();
    }
}

// ============ prep kernels ============
// permuted gate col n -> original row r = (n%4)*512 + n/4  (quad (i,f,g,o) per hidden e)
__global__ void prep_weights(const float* __restrict__ e1Whh,
                             const float* __restrict__ e2Wih, const float* __restrict__ e2Whh,
                             const float* __restrict__ d1Wih, const float* __restrict__ d1Whh,
                             const float* __restrict__ e2bih, const float* __restrict__ e2bhh,
                             const float* __restrict__ d1bih, const float* __restrict__ d1bhh)
{
    int n = blockIdx.y;
    int kk = blockIdx.x * 256 + threadIdx.x;
    if (kk >= K1 + K2 + KD + KD) return;
    int r = (n & 3) * 512 + (n >> 2);
    float v; __half* ph; long o;
    if (kk < K1) {
        v = (kk < 512) ? e1Whh[(long)r * 512 + kk] : 0.f;   // 512..575 pad; 512..545 overwritten by prep_wc
        ph = g_W1; o = (long)n * K1 + kk;
    } else if (kk < K1 + K2) {
        int k = kk - K1;
        v = (k < 512) ? e2Wih[(long)r * 512 + k] : e2Whh[(long)r * 512 + (k - 512)];
        ph = g_W2; o = (long)n * K2 + k;
    } else if (kk < K1 + K2 + KD) {
        int k = kk - (K1 + K2);
        v = d1Whh[(long)r * 512 + k];
        ph = g_WD1; o = (long)n * KD + k;
    } else {
        int k = kk - (K1 + K2 + KD);
        v = d1Wih[(long)r * 512 + k] + d1Whh[(long)r * 512 + k];
        ph = g_WDr; o = (long)n * KD + k;
    }
    ph[o] = __float2half_rn(v);
    if (kk == 0) {
        g_b2[n] = e2bih[r] + e2bhh[r];
        g_bd[n] = d1bih[r] + d1bhh[r];
    }
}

// Wc = e1Wih @ enc_lin_W folded into W1 rows 512..545; b1 = e1Wih·enc_b + biases
__global__ void prep_wc(const float* __restrict__ e1Wih,
                        const float* __restrict__ encW, const float* __restrict__ encb,
                        const float* __restrict__ e1bih, const float* __restrict__ e1bhh)
{
    int n = blockIdx.x;
    int r = (n & 3) * 512 + (n >> 2);
    __shared__ float wr[512];
    for (int e = threadIdx.x; e < 512; e += blockDim.x) wr[e] = e1Wih[(long)r * 512 + e];
    __syncthreads();
    int t = threadIdx.x;
    if (t < POSE) {
        float acc = 0.f;
        for (int e = 0; e < 512; e++) acc = fmaf(wr[e], encW[e * POSE + t], acc);
        g_W1[(long)n * K1 + 512 + t] = __float2half_rn(acc);
    } else if (t == POSE) {
        float acc = e1bih[r] + e1bhh[r];
        for (int e = 0; e < 512; e++) acc = fmaf(wr[e], encb[e], acc);
        g_b1[n] = acc;
    }
}

__global__ void prep_x(const float* __restrict__ x) {
    long idx = (long)blockIdx.x * 256 + threadIdx.x;
    if (idx >= (long)TT * BB * 64) return;
    int c = (int)(idx & 63);
    int b = (int)((idx >> 6) & (BB - 1));
    int t = (int)(idx >> 17);
    float v = (c < POSE) ? x[(long)b * (TT * POSE) + t * POSE + c] : 0.f;
    g_x[idx] = __float2half_rn(v);
}

__global__ void zero_init() {
    long i = (long)blockIdx.x * 256 + threadIdx.x;
    if (i < (long)BE) {
        __half z = __float2half_rn(0.f);
        g_h1[1][i] = z;     // h1(-1) read from slot 1
        g_h2[1][i] = z;     // h2(-1) read from slot 1
        g_c1[i] = 0.f; g_c2[i] = 0.f;
    }
}

__global__ void final_linear(const float* __restrict__ preds,
                             const float* __restrict__ W, const float* __restrict__ bias,
                             float* __restrict__ out)
{
    int bf = blockIdx.x;
    int f = bf % FUT;
    int b = bf / FUT;
    __shared__ float row[512];
    const float* src = preds + ((size_t)f * BB + b) * EE;
    for (int i = threadIdx.x; i < 512; i += blockDim.x) row[i] = src[i];
    __syncthreads();
    int p = threadIdx.x;
    if (p < POSE) {
        const float* w = W + (size_t)p * 512;
        float acc = bias[p];
        for (int e = 0; e < 512; e++) acc = fmaf(row[e], w[e], acc);
        out[(size_t)b * (FUT * POSE) + f * POSE + p] = acc;
    }
}

// ============ launch ============
extern "C" void kernel_launch(void* const* d_in, const int* in_sizes, int n_in,
                              void* d_out, int out_size)
{
    (void)in_sizes; (void)n_in; (void)out_size;
    const float* x     = (const float*)d_in[0];
    const float* encW  = (const float*)d_in[1];
    const float* encb  = (const float*)d_in[2];
    const float* e1Wih = (const float*)d_in[3];
    const float* e1Whh = (const float*)d_in[4];
    const float* e1bih = (const float*)d_in[5];
    const float* e1bhh = (const float*)d_in[6];
    const float* e2Wih = (const float*)d_in[7];
    const float* e2Whh = (const float*)d_in[8];
    const float* e2bih = (const float*)d_in[9];
    const float* e2bhh = (const float*)d_in[10];
    const float* d1Wih = (const float*)d_in[11];
    const float* d1Whh = (const float*)d_in[12];
    const float* d1bih = (const float*)d_in[13];
    const float* d1bhh = (const float*)d_in[14];
    const float* dW    = (const float*)d_in[15];
    const float* db    = (const float*)d_in[16];
    float* out = (float*)d_out;

    float* preds;
    cudaGetSymbolAddress((void**)&preds, g_preds);

    cudaFuncSetAttribute(lstm_persistent, cudaFuncAttributeMaxDynamicSharedMemorySize, SMEM_TOTAL);

    zero_init<<<(BE + 255) / 256, 256>>>();
    prep_weights<<<dim3((K1 + K2 + 2 * KD + 255) / 256, 2048), 256>>>(
        e1Whh, e2Wih, e2Whh, d1Wih, d1Whh, e2bih, e2bhh, d1bih, d1bhh);
    prep_wc<<<2048, 64>>>(e1Wih, encW, encb, e1bih, e1bhh);
    prep_x<<<(int)(((long)TT * BB * 64 + 255) / 256), 256>>>(x);

    // entire recurrence: one persistent launch, device-wide barriers between phases
    lstm_persistent<<<NCTA, 128, SMEM_TOTAL>>>();

    final_linear<<<BB * FUT, 64>>>(preds, dW, db, out);
}